// round 1
// baseline (speedup 1.0000x reference)
#include <cuda_runtime.h>
#include <cstdint>

#define B_ 4
#define C_ 3
#define T_ 103
#define H_ 224
#define W_ 224
#define HW_ (H_ * W_)
#define HW4_ (HW_ / 4)   // 12544
#define NTHREADS 256
#define NBLK_X (HW4_ / NTHREADS)  // 49

__global__ __launch_bounds__(NTHREADS)
void fuse_kernel(const float* __restrict__ video,
                 const float* __restrict__ bbox,
                 const int* __restrict__ index,
                 float* __restrict__ out)
{
    const int bct = blockIdx.y;              // (b*C + c)*T + t
    const int b   = bct / (C_ * T_);
    const int t   = bct % T_;

    __shared__ int s_cx0, s_cx1, s_cy0, s_cy1;   // own clamped mask rect
    __shared__ int s_bx0, s_bx1, s_by0, s_by1;   // perm (index[b]) br rect, unclamped ints
    __shared__ int s_bp;

    if (threadIdx.x == 0) {
        const int bp = index[b];
        s_bp = bp;

        // own bbox -> clamped mask rect
        const float* bb = bbox + ((size_t)b * T_ + t) * 8;
        float x0 = bb[0], x1 = bb[2], x2 = bb[4], x3 = bb[6];
        float y0 = bb[1], y1 = bb[3], y2 = bb[5], y3 = bb[7];
        float xmin = fminf(fminf(x0, x1), fminf(x2, x3));
        float xmax = fmaxf(fmaxf(x0, x1), fmaxf(x2, x3));
        float ymin = fminf(fminf(y0, y1), fminf(y2, y3));
        float ymax = fmaxf(fmaxf(y0, y1), fmaxf(y2, y3));
        s_cx0 = (int)fmaxf(xmin, 0.0f);
        s_cy0 = (int)fmaxf(ymin, 0.0f);
        s_cx1 = (int)fminf(xmax, (float)W_);
        s_cy1 = (int)fminf(ymax, (float)H_);

        // permuted bbox -> unclamped int rect (m_br[index])
        const float* bbp = bbox + ((size_t)bp * T_ + t) * 8;
        float px0 = bbp[0], px1 = bbp[2], px2 = bbp[4], px3 = bbp[6];
        float py0 = bbp[1], py1 = bbp[3], py2 = bbp[5], py3 = bbp[7];
        s_bx0 = (int)fminf(fminf(px0, px1), fminf(px2, px3));
        s_bx1 = (int)fmaxf(fmaxf(px0, px1), fmaxf(px2, px3));
        s_by0 = (int)fminf(fminf(py0, py1), fminf(py2, py3));
        s_by1 = (int)fmaxf(fmaxf(py0, py1), fmaxf(py2, py3));
    }
    __syncthreads();

    const int p = blockIdx.x * NTHREADS + threadIdx.x;   // float4 index in image
    const int h = p / (W_ / 4);
    const int x = (p % (W_ / 4)) * 4;

    const bool rowM  = (h >= s_cy0) & (h <= s_cy1);
    const bool rowBr = (h >= s_by0) & (h <= s_by1);

    bool m[4], bg[4];
    bool anyM = false, anyBg = false;
#pragma unroll
    for (int i = 0; i < 4; i++) {
        const int xi = x + i;
        m[i]  = rowM  & (xi >= s_cx0) & (xi <= s_cx1);
        const bool br = rowBr & (xi >= s_bx0) & (xi <= s_bx1);
        bg[i] = !(br | m[i]);
        anyM  |= m[i];
        anyBg |= bg[i];
    }

    const size_t ownOff  = (size_t)bct * HW_ + (size_t)h * W_ + x;
    const int c = (bct / T_) % C_;
    const size_t permOff = ((((size_t)s_bp * C_ + c) * T_ + t)) * (size_t)HW_
                           + (size_t)h * W_ + x;

    float4 own  = make_float4(0.f, 0.f, 0.f, 0.f);
    float4 perm = make_float4(0.f, 0.f, 0.f, 0.f);
    if (anyM)  own  = *reinterpret_cast<const float4*>(video + ownOff);
    if (anyBg) perm = *reinterpret_cast<const float4*>(video + permOff);

    float4 r;
    r.x = m[0] ? own.x : (bg[0] ? perm.x : 0.0f);
    r.y = m[1] ? own.y : (bg[1] ? perm.y : 0.0f);
    r.z = m[2] ? own.z : (bg[2] ? perm.z : 0.0f);
    r.w = m[3] ? own.w : (bg[3] ? perm.w : 0.0f);

    *reinterpret_cast<float4*>(out + ownOff) = r;
}

extern "C" void kernel_launch(void* const* d_in, const int* in_sizes, int n_in,
                              void* d_out, int out_size)
{
    const float* video = (const float*)d_in[0];
    const float* bbox  = (const float*)d_in[1];
    const int*   index = (const int*)d_in[2];
    float* out = (float*)d_out;

    dim3 grid(NBLK_X, B_ * C_ * T_);
    fuse_kernel<<<grid, NTHREADS>>>(video, bbox, index, out);
}

// round 2
// speedup vs baseline: 1.0729x; 1.0729x over previous
#include <cuda_runtime.h>
#include <cstdint>

#define B_ 4
#define C_ 3
#define T_ 103
#define H_ 224
#define W_ 224
#define HW_ (H_ * W_)
#define W4_ (W_ / 4)        // 56 float4 per row
#define ROWS_PER_BLK 16
#define NIMG (B_ * C_ * T_) // 1236

__global__ __launch_bounds__(224)
void fuse_kernel(const float* __restrict__ video,
                 const float* __restrict__ bbox,
                 const int* __restrict__ index,
                 float* __restrict__ out)
{
    const int bct = blockIdx.y;              // (b*C + c)*T + t
    const int b   = bct / (C_ * T_);
    const int t   = bct % T_;

    __shared__ int s_cx0, s_cx1, s_cy0, s_cy1;   // own clamped mask rect
    __shared__ int s_bx0, s_bx1, s_by0, s_by1;   // perm br rect (unclamped ints)
    __shared__ int s_bp;

    if (threadIdx.x == 0 && threadIdx.y == 0) {
        const int bp = index[b];
        s_bp = bp;

        const float* bb = bbox + ((size_t)b * T_ + t) * 8;
        float xmin = fminf(fminf(bb[0], bb[2]), fminf(bb[4], bb[6]));
        float xmax = fmaxf(fmaxf(bb[0], bb[2]), fmaxf(bb[4], bb[6]));
        float ymin = fminf(fminf(bb[1], bb[3]), fminf(bb[5], bb[7]));
        float ymax = fmaxf(fmaxf(bb[1], bb[3]), fmaxf(bb[5], bb[7]));
        s_cx0 = (int)fmaxf(xmin, 0.0f);
        s_cy0 = (int)fmaxf(ymin, 0.0f);
        s_cx1 = (int)fminf(xmax, (float)W_);
        s_cy1 = (int)fminf(ymax, (float)H_);

        const float* bbp = bbox + ((size_t)bp * T_ + t) * 8;
        s_bx0 = (int)fminf(fminf(bbp[0], bbp[2]), fminf(bbp[4], bbp[6]));
        s_bx1 = (int)fmaxf(fmaxf(bbp[0], bbp[2]), fmaxf(bbp[4], bbp[6]));
        s_by0 = (int)fminf(fminf(bbp[1], bbp[3]), fminf(bbp[5], bbp[7]));
        s_by1 = (int)fmaxf(fmaxf(bbp[1], bbp[3]), fmaxf(bbp[5], bbp[7]));
    }
    __syncthreads();

    const int cx0 = s_cx0, cx1 = s_cx1, cy0 = s_cy0, cy1 = s_cy1;
    const int bx0 = s_bx0, bx1 = s_bx1, by0 = s_by0, by1 = s_by1;
    const int bp  = s_bp;

    const int x  = threadIdx.x * 4;                      // pixel column of chunk
    const int h0 = blockIdx.x * ROWS_PER_BLK + threadIdx.y;

    // ---- x-side classification (computed once, reused for 4 rows) ----
    bool mx[4], brx[4];
#pragma unroll
    for (int i = 0; i < 4; i++) {
        const int xi = x + i;
        mx[i]  = (xi >= cx0) & (xi <= cx1);
        brx[i] = (xi >= bx0) & (xi <= bx1);
    }
    const bool mAllX  = mx[0] & mx[1] & mx[2] & mx[3];
    const bool mAnyX  = mx[0] | mx[1] | mx[2] | mx[3];
    const bool brAnyX = brx[0] | brx[1] | brx[2] | brx[3];

    const int c = (bct / T_) % C_;
    const size_t rowStride4 = (size_t)(4 * W_);
    size_t ownOff  = (size_t)bct * HW_ + (size_t)h0 * W_ + x;
    size_t permOff = (((size_t)bp * C_ + c) * T_ + t) * (size_t)HW_
                     + (size_t)h0 * W_ + x;

#pragma unroll
    for (int j = 0; j < 4; j++) {
        const int h = h0 + 4 * j;
        const bool rowM  = (h >= cy0) & (h <= cy1);
        const bool rowBr = (h >= by0) & (h <= by1);

        const bool chunkMAll  = rowM & mAllX;
        const bool chunkMAny  = rowM & mAnyX;
        const bool chunkBrAny = rowBr & brAnyX;

        float4 r;
        if (chunkMAll) {
            // fully inside own mask: copy own video
            r = *reinterpret_cast<const float4*>(video + ownOff);
        } else if (!chunkMAny && !chunkBrAny) {
            // fully background: copy permuted video
            r = *reinterpret_cast<const float4*>(video + permOff);
        } else {
            // boundary chunk: per-element select
            bool m[4], bg[4];
            bool anyM = false, anyBg = false;
#pragma unroll
            for (int i = 0; i < 4; i++) {
                m[i]  = rowM & mx[i];
                bg[i] = !((rowBr & brx[i]) | m[i]);
                anyM |= m[i];
                anyBg |= bg[i];
            }
            float4 own  = make_float4(0.f, 0.f, 0.f, 0.f);
            float4 perm = make_float4(0.f, 0.f, 0.f, 0.f);
            if (anyM)  own  = *reinterpret_cast<const float4*>(video + ownOff);
            if (anyBg) perm = *reinterpret_cast<const float4*>(video + permOff);
            r.x = m[0] ? own.x : (bg[0] ? perm.x : 0.0f);
            r.y = m[1] ? own.y : (bg[1] ? perm.y : 0.0f);
            r.z = m[2] ? own.z : (bg[2] ? perm.z : 0.0f);
            r.w = m[3] ? own.w : (bg[3] ? perm.w : 0.0f);
        }
        *reinterpret_cast<float4*>(out + ownOff) = r;

        ownOff  += rowStride4;
        permOff += rowStride4;
    }
}

extern "C" void kernel_launch(void* const* d_in, const int* in_sizes, int n_in,
                              void* d_out, int out_size)
{
    const float* video = (const float*)d_in[0];
    const float* bbox  = (const float*)d_in[1];
    const int*   index = (const int*)d_in[2];
    float* out = (float*)d_out;

    dim3 block(W4_, 4);                    // 224 threads
    dim3 grid(H_ / ROWS_PER_BLK, NIMG);    // (14, 1236)
    fuse_kernel<<<grid, block>>>(video, bbox, index, out);
}